// round 6
// baseline (speedup 1.0000x reference)
#include <cuda_runtime.h>
#include <math.h>

#define BB 2
#define NN 8192
#define DD 64
#define KNBR 16
#define NPTS (BB*NN)          // 16384
#define ROWS (NPTS*KNBR)      // 262144

// ---- spatial grid for KNN ----
#define GD   64
#define GD3  (GD*GD*GD)       // 262144
#define CPT  256              // cells per scan thread (1024*256 == GD3)
#define XMIN (-8.0f)
#define HCELL 0.25f
#define INVH  4.0f

// ---------------- scratch (static device arrays; no allocation) ----------------
__device__ float  g_q  [NPTS*DD];
__device__ float  g_kf [NPTS*DD];
__device__ float  g_vf [NPTS*DD];
__device__ int    g_knn[ROWS];
__device__ float  g_res[NPTS*DD];
__device__ float  g_sum[DD];
__device__ float  g_sumsq[DD];
__device__ int    g_cnt  [BB*GD3];
__device__ int    g_start[BB*(GD3+1)];
__device__ int    g_cur  [BB*GD3];
__device__ float4 g_pts  [NPTS];     // cell-sorted (x,y,z,|p|^2) per batch
__device__ int    g_sid  [NPTS];     // original index of sorted point

// ---------------- packed f32x2 helpers ----------------
__device__ __forceinline__ void fma2(unsigned long long &d, unsigned long long a, unsigned long long b) {
    asm("fma.rn.f32x2 %0, %1, %2, %0;" : "+l"(d) : "l"(a), "l"(b));
}
__device__ __forceinline__ unsigned long long pk2(float lo, float hi) {
    unsigned long long r; asm("mov.b64 %0, {%1,%2};" : "=l"(r) : "f"(lo), "f"(hi)); return r;
}
__device__ __forceinline__ float2 up2(unsigned long long v) {
    float2 r; asm("mov.b64 {%0,%1}, %2;" : "=f"(r.x), "=f"(r.y) : "l"(v)); return r;
}

// 128x64 GEMM slice. sA: k-major [64][132]; sW: row-major [64][64].
__device__ __forceinline__ void gemm_f32x2(const float* __restrict__ sA, const float* __restrict__ sW,
                                           int mbase, int c0,
                                           unsigned long long* a0, unsigned long long* a1)
{
    #pragma unroll 4
    for (int kk = 0; kk < 64; kk++) {
        const ulonglong2* ap = (const ulonglong2*)(sA + kk*132 + mbase);   // broadcast LDS.128
        float2 w = *(const float2*)(sW + kk*64 + c0);                      // LDS.64
        unsigned long long w0 = pk2(w.x, w.x);
        unsigned long long w1 = pk2(w.y, w.y);
        ulonglong2 A0 = ap[0], A1 = ap[1];
        fma2(a0[0], A0.x, w0); fma2(a1[0], A0.x, w1);
        fma2(a0[1], A0.y, w0); fma2(a1[1], A0.y, w1);
        fma2(a0[2], A1.x, w0); fma2(a1[2], A1.x, w1);
        fma2(a0[3], A1.y, w0); fma2(a1[3], A1.y, w1);
        ulonglong2 A2 = ap[2], A3 = ap[3];
        fma2(a0[4], A2.x, w0); fma2(a1[4], A2.x, w1);
        fma2(a0[5], A2.y, w0); fma2(a1[5], A2.y, w1);
        fma2(a0[6], A3.x, w0); fma2(a1[6], A3.x, w1);
        fma2(a0[7], A3.y, w0); fma2(a1[7], A3.y, w1);
    }
}

// ---------------- grid build ----------------
__device__ __forceinline__ int cellCoord(float v) {
    int c = (int)((v - XMIN) * INVH);
    return min(max(c, 0), GD-1);
}

__global__ void __launch_bounds__(1024) zero_kernel() {
    int i = blockIdx.x * 1024 + threadIdx.x;       // 512*1024 == BB*GD3
    g_cnt[i] = 0;
    if (i < 64) { g_sum[i] = 0.f; g_sumsq[i] = 0.f; }
}

__global__ void __launch_bounds__(256) count_kernel(const float* __restrict__ xyz) {
    int t = blockIdx.x * 256 + threadIdx.x;        // 64*256 == NPTS
    int b = t >> 13, i = t & (NN-1);
    const float* p = xyz + ((size_t)b*NN + i)*3;
    float x = p[0], y = p[1], z = p[2];
    int c = (cellCoord(z)*GD + cellCoord(y))*GD + cellCoord(x);
    atomicAdd(&g_cnt[b*GD3 + c], 1);
}

__global__ void __launch_bounds__(1024) scan_kernel() {
    __shared__ int ssum[1024];
    int b = blockIdx.x, tid = threadIdx.x;
    const int* cnt = g_cnt + b*GD3;
    int* start = g_start + b*(GD3+1);
    int base = tid * CPT;
    int s = 0;
    for (int k = 0; k < CPT; k++) s += cnt[base + k];
    ssum[tid] = s;
    __syncthreads();
    for (int d = 1; d < 1024; d <<= 1) {
        int v = (tid >= d) ? ssum[tid - d] : 0;
        __syncthreads();
        ssum[tid] += v;
        __syncthreads();
    }
    int run = (tid == 0) ? 0 : ssum[tid - 1];
    for (int k = 0; k < CPT; k++) {
        start[base + k] = run;
        g_cur[b*GD3 + base + k] = run;
        run += cnt[base + k];
    }
    if (tid == 1023) start[GD3] = run;
}

__global__ void __launch_bounds__(256) scatter_kernel(const float* __restrict__ xyz) {
    int t = blockIdx.x * 256 + threadIdx.x;
    int b = t >> 13, i = t & (NN-1);
    const float* p = xyz + ((size_t)b*NN + i)*3;
    float x = p[0], y = p[1], z = p[2];
    int c = (cellCoord(z)*GD + cellCoord(y))*GD + cellCoord(x);
    int pos = atomicAdd(&g_cur[b*GD3 + c], 1);
    g_pts[b*NN + pos] = make_float4(x, y, z, fmaf(z, z, fmaf(y, y, x*x)));
    g_sid[b*NN + pos] = i;
}

// ---------------- KNN: warp-per-query expanding rings (exact) ----------------
__device__ __forceinline__ void insert16(float d, int idx, float* d16, int* i16, float& worst) {
    bool done = false;
    #pragma unroll
    for (int s = 0; s < KNBR; s++)
        if (!done && d16[s] == worst) { d16[s] = d; i16[s] = idx; done = true; }
    worst = d16[0];
    #pragma unroll
    for (int s = 1; s < KNBR; s++) worst = fmaxf(worst, d16[s]);
}

// lanes evaluate a contiguous run [j0,j1) strided by 32 (coalesced LDG.128)
__device__ __forceinline__ void evalRunW(const float4* __restrict__ pts, int j0, int j1, int lane,
                                         float4 q, float* d16, int* i16, float& worst) {
    for (int j = j0 + lane; j < j1; j += 32) {
        float4 p = pts[j];
        float dot = fmaf(q.z, p.z, fmaf(q.y, p.y, q.x*p.x));
        float d = q.w + p.w - 2.0f * dot;       // same expansion form as reference
        if (d < worst) insert16(d, j, d16, i16, worst);
    }
}

__global__ void __launch_bounds__(256) knn_search_kernel() {
    int warp = (blockIdx.x * 256 + threadIdx.x) >> 5;   // 0..NPTS-1 : one warp per query
    int lane = threadIdx.x & 31;
    int b = warp >> 13;
    float4 q = g_pts[warp];
    int cx = cellCoord(q.x), cy = cellCoord(q.y), cz = cellCoord(q.z);
    const int* start = g_start + b*(GD3+1);
    const float4* pts = g_pts + (size_t)b*NN;

    float d16[KNBR]; int i16[KNBR];
    #pragma unroll
    for (int s = 0; s < KNBR; s++) { d16[s] = 3.4e38f; i16[s] = 0; }
    float worst = 3.4e38f;

    // expanding Chebyshev rings around the query's cell (face-only; x-run coalesced)
    for (int s = 0; s < GD; s++) {
        int xlo = max(cx - s, 0), xhi = min(cx + s, GD-1);
        int zlo = max(cz - s, 0), zhi = min(cz + s, GD-1);
        for (int zz = zlo; zz <= zhi; zz++) {
            int az = (zz > cz) ? (zz - cz) : (cz - zz);
            int rowz = zz * GD;
            if (az == s) {
                int ylo = max(cy - s, 0), yhi = min(cy + s, GD-1);
                for (int yy = ylo; yy <= yhi; yy++) {
                    int cb = (rowz + yy) * GD;
                    evalRunW(pts, start[cb + xlo], start[cb + xhi + 1], lane, q, d16, i16, worst);
                }
            } else {
                int y0 = cy - s, y1 = cy + s;
                if (y0 >= 0) {
                    int cb = (rowz + y0) * GD;
                    evalRunW(pts, start[cb + xlo], start[cb + xhi + 1], lane, q, d16, i16, worst);
                }
                if (y1 <= GD-1) {
                    int cb = (rowz + y1) * GD;
                    evalRunW(pts, start[cb + xlo], start[cb + xhi + 1], lane, q, d16, i16, worst);
                }
                int yi0 = max(cy - s + 1, 0), yi1 = min(cy + s - 1, GD-1);
                int x0 = cx - s, x1 = cx + s;
                bool h0 = (x0 >= 0), h1 = (x1 <= GD-1);
                for (int yy = yi0; yy <= yi1; yy++) {
                    int cb = (rowz + yy) * GD;
                    if (h0) evalRunW(pts, start[cb + x0], start[cb + x0 + 1], lane, q, d16, i16, worst);
                    if (h1) evalRunW(pts, start[cb + x1], start[cb + x1 + 1], lane, q, d16, i16, worst);
                }
            }
        }
        // sound termination: >=16 evaluated candidates are <= (s*h)^2 - margin,
        // while every unscanned point is >= s*h away  -> exact top-16 already held
        float bnd = (float)s * HCELL;
        bnd = bnd*bnd - 1e-3f;
        int cnt = 0;
        #pragma unroll
        for (int i = 0; i < KNBR; i++) cnt += (d16[i] <= bnd) ? 1 : 0;
        #pragma unroll
        for (int o = 16; o; o >>= 1) cnt += __shfl_xor_sync(0xffffffffu, cnt, o);
        if (cnt >= KNBR) break;
    }

    // exact warp merge: extract global 16 smallest (every global top-16 element
    // is in its evaluating lane's local top-16)
    int outIdx[KNBR];
    #pragma unroll
    for (int m = 0; m < KNBR; m++) {
        float lm = d16[0]; int lp = 0;
        #pragma unroll
        for (int i = 1; i < KNBR; i++) if (d16[i] < lm) { lm = d16[i]; lp = i; }
        float gmin = lm;
        #pragma unroll
        for (int o = 16; o; o >>= 1) gmin = fminf(gmin, __shfl_xor_sync(0xffffffffu, gmin, o));
        unsigned msk = __ballot_sync(0xffffffffu, lm == gmin);
        int winner = __ffs(msk) - 1;
        int widx = __shfl_sync(0xffffffffu, i16[lp], winner);
        if (lane == winner) d16[lp] = 3.4e38f;
        outIdx[m] = widx;
    }

    int qi = g_sid[warp];
    size_t ob = ((size_t)(b*NN + qi)) * KNBR;
    if (lane < KNBR)
        g_knn[ob + lane] = g_sid[(size_t)b*NN + outIdx[lane]];
}

// ---------------- K1: projections q,k,v = feats @ W ----------------
#define PROJ_SMEM ((64*132 + 64*64)*4)
__global__ void __launch_bounds__(256) proj_kernel(
    const float* __restrict__ feats,
    const float* __restrict__ wq, const float* __restrict__ wk, const float* __restrict__ wv)
{
    extern __shared__ float sm[];
    float* sFt = sm;            // [64][132] feats^T (k-major)
    float* sW  = sm + 64*132;   // [64][64]
    int tid = threadIdx.x;
    int R0 = blockIdx.x * 128;
    for (int i = tid; i < 128*16; i += 256) {
        int r = i >> 4, c4 = (i & 15) << 2;
        float4 v = *(const float4*)(feats + (size_t)(R0 + r)*64 + c4);
        sFt[(c4+0)*132 + r] = v.x;
        sFt[(c4+1)*132 + r] = v.y;
        sFt[(c4+2)*132 + r] = v.z;
        sFt[(c4+3)*132 + r] = v.w;
    }
    int tm = tid >> 5, tn = tid & 31, c0 = tn * 2;
    int mbase = tm << 4;
    const float* Ws[3] = {wq, wk, wv};
    float* Os[3] = {g_q, g_kf, g_vf};
    for (int mat = 0; mat < 3; mat++) {
        __syncthreads();
        for (int i = tid; i < 1024; i += 256)
            *(float4*)(sW + i*4) = *(const float4*)(Ws[mat] + i*4);
        __syncthreads();
        unsigned long long a0[8], a1[8];
        #pragma unroll
        for (int p = 0; p < 8; p++) { a0[p] = 0ull; a1[p] = 0ull; }
        gemm_f32x2(sFt, sW, mbase, c0, a0, a1);
        float* O = Os[mat];
        #pragma unroll
        for (int p = 0; p < 8; p++) {
            float2 r0 = up2(a0[p]);
            float2 r1 = up2(a1[p]);
            *(float2*)(O + (size_t)(R0 + mbase + 2*p)*64 + c0)   = make_float2(r0.x, r1.x);
            *(float2*)(O + (size_t)(R0 + mbase + 2*p+1)*64 + c0) = make_float2(r0.y, r1.y);
        }
    }
}

// ---------------- K3: mega fused kernel ----------------
#define FUSED_SMEM ((64*132 + 3*64*64 + 192 + 256 + 128)*4)
__global__ void __launch_bounds__(256, 2) fused_kernel(
    const float* __restrict__ xyz, const float* __restrict__ feats,
    const float* __restrict__ w1d, const float* __restrict__ b1d,
    const float* __restrict__ w2d, const float* __restrict__ b2d,
    const float* __restrict__ w1g, const float* __restrict__ b1g,
    const float* __restrict__ w2g, const float* __restrict__ b2g)
{
    extern __shared__ float sm[];
    float* sA   = sm;                 // [64][132]
    float* sW2d = sA   + 64*132;      // [64][64]
    float* sW1g = sW2d + 4096;
    float* sW2g = sW1g + 4096;
    float* sW1d = sW2g + 4096;        // [3][64]
    float* sB   = sW1d + 192;         // b1d|b2d|b1g|b2g
    int*   sIdx = (int*)(sB + 256);   // [128]
    int tid = threadIdx.x;

    for (int i = tid; i < 1024; i += 256) {
        *(float4*)(sW2d + i*4) = *(const float4*)(w2d + i*4);
        *(float4*)(sW1g + i*4) = *(const float4*)(w1g + i*4);
        *(float4*)(sW2g + i*4) = *(const float4*)(w2g + i*4);
    }
    if (tid < 192) sW1d[tid] = w1d[tid];
    if (tid < 64) { sB[tid] = b1d[tid]; sB[64+tid] = b2d[tid]; sB[128+tid] = b1g[tid]; sB[192+tid] = b2g[tid]; }

    int R0 = blockIdx.x * 128;
    int P0 = blockIdx.x * 8;
    int b  = P0 >> 13;
    __syncthreads();

    // ---- stage H1 = relu(dxyz @ W1d + b1d) into sA (k-major) ----
    {
        int m   = tid >> 1;
        int row = R0 + m;
        int pn  = row >> 4;
        int nl  = pn & (NN - 1);
        int j   = g_knn[row];
        if ((tid & 1) == 0) sIdx[m] = j;
        const float* xb = xyz + (size_t)b * NN * 3;
        float dx = xb[nl*3+0] - xb[j*3+0];
        float dy = xb[nl*3+1] - xb[j*3+1];
        float dz = xb[nl*3+2] - xb[j*3+2];
        int cb = (tid & 1) * 32;
        #pragma unroll 8
        for (int c = 0; c < 32; c++) {
            int cc = cb + c;
            float h = fmaf(dz, sW1d[128+cc], fmaf(dy, sW1d[64+cc], fmaf(dx, sW1d[cc], sB[cc])));
            sA[cc*132 + m] = fmaxf(h, 0.f);
        }
    }
    __syncthreads();

    int tm = tid >> 5, tn = tid & 31, c0 = tn * 2;
    int mbase = tm << 4;
    int pn0 = P0 + tm;

    // ---- GEMM1: pos = H1 @ W2d + b2d ----
    unsigned long long a0[8], a1[8];
    {
        unsigned long long bb0 = pk2(sB[64+c0],   sB[64+c0]);
        unsigned long long bb1 = pk2(sB[64+c0+1], sB[64+c0+1]);
        #pragma unroll
        for (int p = 0; p < 8; p++) { a0[p] = bb0; a1[p] = bb1; }
        gemm_f32x2(sA, sW2d, mbase, c0, a0, a1);
    }
    __syncthreads();

    // ---- epilogue: x = q - kf + pos -> sA ; val = vf + pos -> v0/v1 ----
    float v0[KNBR], v1[KNBR];
    {
        float2 qv = *(const float2*)(g_q + (size_t)pn0*64 + c0);
        #pragma unroll
        for (int p = 0; p < 8; p++) {
            float2 ps0 = up2(a0[p]);
            float2 ps1 = up2(a1[p]);
            int j0 = sIdx[mbase + 2*p];
            int j1 = sIdx[mbase + 2*p + 1];
            size_t gp0 = ((size_t)(b*NN + j0))*64 + c0;
            size_t gp1 = ((size_t)(b*NN + j1))*64 + c0;
            float2 kf0 = *(const float2*)(g_kf + gp0);
            float2 kf1 = *(const float2*)(g_kf + gp1);
            float2 vf0 = *(const float2*)(g_vf + gp0);
            float2 vf1 = *(const float2*)(g_vf + gp1);
            v0[2*p]   = vf0.x + ps0.x;  v1[2*p]   = vf0.y + ps1.x;
            v0[2*p+1] = vf1.x + ps0.y;  v1[2*p+1] = vf1.y + ps1.y;
            *(float2*)(sA + c0*132     + mbase + 2*p) = make_float2(qv.x - kf0.x + ps0.x, qv.x - kf1.x + ps0.y);
            *(float2*)(sA + (c0+1)*132 + mbase + 2*p) = make_float2(qv.y - kf0.y + ps1.x, qv.y - kf1.y + ps1.y);
        }
    }
    __syncthreads();

    // ---- GEMM2: g1 = relu(x @ W1g + b1g) ----
    {
        unsigned long long bb0 = pk2(sB[128+c0],   sB[128+c0]);
        unsigned long long bb1 = pk2(sB[128+c0+1], sB[128+c0+1]);
        #pragma unroll
        for (int p = 0; p < 8; p++) { a0[p] = bb0; a1[p] = bb1; }
        gemm_f32x2(sA, sW1g, mbase, c0, a0, a1);
    }
    __syncthreads();
    #pragma unroll
    for (int p = 0; p < 8; p++) {
        float2 r0 = up2(a0[p]), r1 = up2(a1[p]);
        *(float2*)(sA + c0*132     + mbase + 2*p) = make_float2(fmaxf(r0.x,0.f), fmaxf(r0.y,0.f));
        *(float2*)(sA + (c0+1)*132 + mbase + 2*p) = make_float2(fmaxf(r1.x,0.f), fmaxf(r1.y,0.f));
    }
    __syncthreads();

    // ---- GEMM3: logits = g1 @ W2g + b2g ----
    {
        unsigned long long bb0 = pk2(sB[192+c0],   sB[192+c0]);
        unsigned long long bb1 = pk2(sB[192+c0+1], sB[192+c0+1]);
        #pragma unroll
        for (int p = 0; p < 8; p++) { a0[p] = bb0; a1[p] = bb1; }
        gemm_f32x2(sA, sW2g, mbase, c0, a0, a1);
    }

    // ---- softmax over K (thread-local) + weighted sum + residual ----
    float t0a[KNBR], t1a[KNBR];
    #pragma unroll
    for (int p = 0; p < 8; p++) {
        float2 r0 = up2(a0[p]), r1 = up2(a1[p]);
        t0a[2*p] = r0.x; t0a[2*p+1] = r0.y;
        t1a[2*p] = r1.x; t1a[2*p+1] = r1.y;
    }
    float m0 = t0a[0], m1 = t1a[0];
    #pragma unroll
    for (int s = 1; s < KNBR; s++) { m0 = fmaxf(m0, t0a[s]); m1 = fmaxf(m1, t1a[s]); }
    float s0 = 0.f, s1 = 0.f;
    #pragma unroll
    for (int s = 0; s < KNBR; s++) {
        t0a[s] = __expf(t0a[s] - m0);  s0 += t0a[s];
        t1a[s] = __expf(t1a[s] - m1);  s1 += t1a[s];
    }
    float r0 = 0.f, r1 = 0.f;
    #pragma unroll
    for (int s = 0; s < KNBR; s++) { r0 = fmaf(t0a[s], v0[s], r0); r1 = fmaf(t1a[s], v1[s], r1); }
    float2 fv = *(const float2*)(feats + (size_t)pn0*64 + c0);
    r0 = r0 / s0 + fv.x;
    r1 = r1 / s1 + fv.y;
    *(float2*)(g_res + (size_t)pn0*64 + c0) = make_float2(r0, r1);

    // ---- BN partial sums ----
    __syncthreads();
    if (tid < 128) sA[tid] = 0.f;
    __syncthreads();
    atomicAdd(&sA[c0],      r0);
    atomicAdd(&sA[c0+1],    r1);
    atomicAdd(&sA[64+c0],   r0*r0);
    atomicAdd(&sA[64+c0+1], r1*r1);
    __syncthreads();
    if (tid < 64) {
        atomicAdd(&g_sum[tid],   sA[tid]);
        atomicAdd(&g_sumsq[tid], sA[64+tid]);
    }
}

// ---------------- K4: BatchNorm apply ----------------
__global__ void __launch_bounds__(256) bn_kernel(
    const float* __restrict__ bn_gamma, const float* __restrict__ bn_beta,
    float* __restrict__ out)
{
    int idx = blockIdx.x * 256 + threadIdx.x;
    int c = idx & 63;
    float inv = 1.0f / (float)NPTS;
    float mean = g_sum[c] * inv;
    float var  = g_sumsq[c] * inv - mean * mean;
    out[idx] = (g_res[idx] - mean) * rsqrtf(var + 1e-5f) * bn_gamma[c] + bn_beta[c];
}

// ---------------- launch ----------------
extern "C" void kernel_launch(void* const* d_in, const int* in_sizes, int n_in,
                              void* d_out, int out_size)
{
    const float* xyz   = (const float*)d_in[0];
    const float* feats = (const float*)d_in[1];
    const float* wq    = (const float*)d_in[2];
    const float* wk    = (const float*)d_in[3];
    const float* wv    = (const float*)d_in[4];
    const float* dw1   = (const float*)d_in[5];
    const float* db1   = (const float*)d_in[6];
    const float* dw2   = (const float*)d_in[7];
    const float* db2   = (const float*)d_in[8];
    const float* gw1   = (const float*)d_in[9];
    const float* gb1   = (const float*)d_in[10];
    const float* gw2   = (const float*)d_in[11];
    const float* gb2   = (const float*)d_in[12];
    const float* bng   = (const float*)d_in[13];
    const float* bnb   = (const float*)d_in[14];
    float* out = (float*)d_out;

    cudaFuncSetAttribute(proj_kernel,  cudaFuncAttributeMaxDynamicSharedMemorySize, PROJ_SMEM);
    cudaFuncSetAttribute(fused_kernel, cudaFuncAttributeMaxDynamicSharedMemorySize, FUSED_SMEM);

    zero_kernel      <<<(BB*GD3)/1024, 1024>>>();
    count_kernel     <<<NPTS/256, 256>>>(xyz);
    scan_kernel      <<<BB, 1024>>>();
    scatter_kernel   <<<NPTS/256, 256>>>(xyz);
    knn_search_kernel<<<NPTS/8, 256>>>();     // 8 warps/block, 1 warp per query
    proj_kernel      <<<128, 256, PROJ_SMEM>>>(feats, wq, wk, wv);
    fused_kernel     <<<2048, 256, FUSED_SMEM>>>(xyz, feats, dw1, db1, dw2, db2, gw1, gb1, gw2, gb2);
    bn_kernel        <<<4096, 256>>>(bng, bnb, out);
}

// round 7
// speedup vs baseline: 2.0332x; 2.0332x over previous
#include <cuda_runtime.h>
#include <math.h>

#define BB 2
#define NN 8192
#define DD 64
#define KNBR 16
#define NPTS (BB*NN)          // 16384
#define ROWS (NPTS*KNBR)      // 262144

// ---- spatial grid for KNN ----
#define GD   64
#define GD3  (GD*GD*GD)       // 262144
#define CPT  256              // cells per scan thread (1024*256 == GD3)
#define XMIN (-8.0f)
#define HCELL 0.25f
#define INVH  4.0f

// ---------------- scratch (static device arrays; no allocation) ----------------
__device__ float  g_q  [NPTS*DD];
__device__ float  g_kf [NPTS*DD];
__device__ float  g_vf [NPTS*DD];
__device__ int    g_knn[ROWS];
__device__ float  g_res[NPTS*DD];
__device__ float  g_sum[DD];
__device__ float  g_sumsq[DD];
__device__ int    g_cnt  [BB*GD3];
__device__ int    g_start[BB*(GD3+1)];
__device__ int    g_cur  [BB*GD3];
__device__ float4 g_pts  [NPTS];     // cell-sorted (x,y,z,|p|^2) per batch
__device__ int    g_sid  [NPTS];     // original index of sorted point

// ---------------- packed f32x2 helpers ----------------
__device__ __forceinline__ void fma2(unsigned long long &d, unsigned long long a, unsigned long long b) {
    asm("fma.rn.f32x2 %0, %1, %2, %0;" : "+l"(d) : "l"(a), "l"(b));
}
__device__ __forceinline__ unsigned long long pk2(float lo, float hi) {
    unsigned long long r; asm("mov.b64 %0, {%1,%2};" : "=l"(r) : "f"(lo), "f"(hi)); return r;
}
__device__ __forceinline__ float2 up2(unsigned long long v) {
    float2 r; asm("mov.b64 {%0,%1}, %2;" : "=f"(r.x), "=f"(r.y) : "l"(v)); return r;
}

// 128x64 GEMM slice. sA: k-major [64][132]; sW: row-major [64][64].
__device__ __forceinline__ void gemm_f32x2(const float* __restrict__ sA, const float* __restrict__ sW,
                                           int mbase, int c0,
                                           unsigned long long* a0, unsigned long long* a1)
{
    #pragma unroll 4
    for (int kk = 0; kk < 64; kk++) {
        const ulonglong2* ap = (const ulonglong2*)(sA + kk*132 + mbase);   // broadcast LDS.128
        float2 w = *(const float2*)(sW + kk*64 + c0);                      // LDS.64
        unsigned long long w0 = pk2(w.x, w.x);
        unsigned long long w1 = pk2(w.y, w.y);
        ulonglong2 A0 = ap[0], A1 = ap[1];
        fma2(a0[0], A0.x, w0); fma2(a1[0], A0.x, w1);
        fma2(a0[1], A0.y, w0); fma2(a1[1], A0.y, w1);
        fma2(a0[2], A1.x, w0); fma2(a1[2], A1.x, w1);
        fma2(a0[3], A1.y, w0); fma2(a1[3], A1.y, w1);
        ulonglong2 A2 = ap[2], A3 = ap[3];
        fma2(a0[4], A2.x, w0); fma2(a1[4], A2.x, w1);
        fma2(a0[5], A2.y, w0); fma2(a1[5], A2.y, w1);
        fma2(a0[6], A3.x, w0); fma2(a1[6], A3.x, w1);
        fma2(a0[7], A3.y, w0); fma2(a1[7], A3.y, w1);
    }
}

// ---------------- grid build ----------------
__device__ __forceinline__ int cellCoord(float v) {
    int c = (int)((v - XMIN) * INVH);
    return min(max(c, 0), GD-1);
}

__global__ void __launch_bounds__(1024) zero_kernel() {
    int i = blockIdx.x * 1024 + threadIdx.x;       // 512*1024 == BB*GD3
    g_cnt[i] = 0;
    if (i < 64) { g_sum[i] = 0.f; g_sumsq[i] = 0.f; }
}

__global__ void __launch_bounds__(256) count_kernel(const float* __restrict__ xyz) {
    int t = blockIdx.x * 256 + threadIdx.x;        // 64*256 == NPTS
    int b = t >> 13, i = t & (NN-1);
    const float* p = xyz + ((size_t)b*NN + i)*3;
    float x = p[0], y = p[1], z = p[2];
    int c = (cellCoord(z)*GD + cellCoord(y))*GD + cellCoord(x);
    atomicAdd(&g_cnt[b*GD3 + c], 1);
}

__global__ void __launch_bounds__(1024) scan_kernel() {
    __shared__ int ssum[1024];
    int b = blockIdx.x, tid = threadIdx.x;
    const int* cnt = g_cnt + b*GD3;
    int* start = g_start + b*(GD3+1);
    int base = tid * CPT;
    int s = 0;
    for (int k = 0; k < CPT; k++) s += cnt[base + k];
    ssum[tid] = s;
    __syncthreads();
    for (int d = 1; d < 1024; d <<= 1) {
        int v = (tid >= d) ? ssum[tid - d] : 0;
        __syncthreads();
        ssum[tid] += v;
        __syncthreads();
    }
    int run = (tid == 0) ? 0 : ssum[tid - 1];
    for (int k = 0; k < CPT; k++) {
        start[base + k] = run;
        g_cur[b*GD3 + base + k] = run;
        run += cnt[base + k];
    }
    if (tid == 1023) start[GD3] = run;
}

__global__ void __launch_bounds__(256) scatter_kernel(const float* __restrict__ xyz) {
    int t = blockIdx.x * 256 + threadIdx.x;
    int b = t >> 13, i = t & (NN-1);
    const float* p = xyz + ((size_t)b*NN + i)*3;
    float x = p[0], y = p[1], z = p[2];
    int c = (cellCoord(z)*GD + cellCoord(y))*GD + cellCoord(x);
    int pos = atomicAdd(&g_cur[b*GD3 + c], 1);
    g_pts[b*NN + pos] = make_float4(x, y, z, fmaf(z, z, fmaf(y, y, x*x)));
    g_sid[b*NN + pos] = i;
}

// ---------------- KNN: warp-per-query two-phase box scan (exact) ----------------
__device__ __forceinline__ void insert16(float d, int idx, float* d16, int* i16, float& worst) {
    bool done = false;
    #pragma unroll
    for (int s = 0; s < KNBR; s++)
        if (!done && d16[s] == worst) { d16[s] = d; i16[s] = idx; done = true; }
    worst = d16[0];
    #pragma unroll
    for (int s = 1; s < KNBR; s++) worst = fmaxf(worst, d16[s]);
}

__global__ void __launch_bounds__(256) knn_search_kernel() {
    int warp = (blockIdx.x * 256 + threadIdx.x) >> 5;   // one warp per query
    int lane = threadIdx.x & 31;
    int b = warp >> 13;
    float4 q = g_pts[warp];
    int cx = cellCoord(q.x), cy = cellCoord(q.y), cz = cellCoord(q.z);
    const int* start = g_start + b*(GD3+1);
    const float4* pts = g_pts + (size_t)b*NN;

    // ---- Phase A: grow cube (counts only) until >= 16 points inside ----
    int s;
    for (s = 1; s < GD; s++) {
        int zlo = max(cz-s,0), zhi = min(cz+s,GD-1);
        int ylo = max(cy-s,0), yhi = min(cy+s,GD-1);
        int xlo = max(cx-s,0), xhi = min(cx+s,GD-1);
        int W = yhi - ylo + 1;
        int nrows = (zhi - zlo + 1) * W;
        int cnt = 0;
        for (int r0 = lane; r0 < nrows; r0 += 32) {
            int zz = zlo + r0 / W, yy = ylo + r0 % W;
            int cb = (zz*GD + yy) * GD;
            cnt += start[cb + xhi + 1] - start[cb + xlo];
        }
        #pragma unroll
        for (int o = 16; o; o >>= 1) cnt += __shfl_xor_sync(0xffffffffu, cnt, o);
        if (cnt >= KNBR) break;
    }

    // >=16 points within Euclid r = (s+1)*h*sqrt(3) of the query
    // scan all cells with min distance < r: Chebyshev offset t with (t-1)*h < r
    float r = (float)(s + 1) * HCELL * 1.7320509f;
    int S = (int)ceilf(r * INVH + 1e-3f) + 1;
    if (S > GD) S = GD;

    // ---- Phase B: scan box, rows distributed across lanes ----
    float d16[KNBR]; int i16[KNBR];
    #pragma unroll
    for (int i = 0; i < KNBR; i++) { d16[i] = 3.4e38f; i16[i] = 0; }
    float worst = 3.4e38f;
    {
        int zlo = max(cz-S,0), zhi = min(cz+S,GD-1);
        int ylo = max(cy-S,0), yhi = min(cy+S,GD-1);
        int xlo = max(cx-S,0), xhi = min(cx+S,GD-1);
        int W = yhi - ylo + 1;
        int nrows = (zhi - zlo + 1) * W;
        for (int r0 = lane; r0 < nrows; r0 += 32) {
            int zz = zlo + r0 / W, yy = ylo + r0 % W;
            int cb = (zz*GD + yy) * GD;
            int j0 = start[cb + xlo], j1 = start[cb + xhi + 1];
            for (int j = j0; j < j1; j++) {
                float4 p = pts[j];
                float dot = fmaf(q.z, p.z, fmaf(q.y, p.y, q.x*p.x));
                float d = q.w + p.w - 2.0f * dot;   // same expansion form as reference
                if (d < worst) insert16(d, j, d16, i16, worst);
            }
        }
    }

    // ---- exact warp merge: extract the 16 globally smallest ----
    int outIdx[KNBR];
    #pragma unroll
    for (int m = 0; m < KNBR; m++) {
        float lm = d16[0]; int lp = 0;
        #pragma unroll
        for (int i = 1; i < KNBR; i++) if (d16[i] < lm) { lm = d16[i]; lp = i; }
        float gmin = lm;
        #pragma unroll
        for (int o = 16; o; o >>= 1) gmin = fminf(gmin, __shfl_xor_sync(0xffffffffu, gmin, o));
        unsigned msk = __ballot_sync(0xffffffffu, lm == gmin);
        int winner = __ffs(msk) - 1;
        int widx = __shfl_sync(0xffffffffu, i16[lp], winner);
        if (lane == winner) d16[lp] = 3.4e38f;
        outIdx[m] = widx;
    }

    int qi = g_sid[warp];
    size_t ob = ((size_t)(b*NN + qi)) * KNBR;
    if (lane < KNBR)
        g_knn[ob + lane] = g_sid[(size_t)b*NN + outIdx[lane]];
}

// ---------------- K1: projections q,k,v = feats @ W ----------------
#define PROJ_SMEM ((64*132 + 64*64)*4)
__global__ void __launch_bounds__(256) proj_kernel(
    const float* __restrict__ feats,
    const float* __restrict__ wq, const float* __restrict__ wk, const float* __restrict__ wv)
{
    extern __shared__ float sm[];
    float* sFt = sm;            // [64][132] feats^T (k-major)
    float* sW  = sm + 64*132;   // [64][64]
    int tid = threadIdx.x;
    int R0 = blockIdx.x * 128;
    for (int i = tid; i < 128*16; i += 256) {
        int r = i >> 4, c4 = (i & 15) << 2;
        float4 v = *(const float4*)(feats + (size_t)(R0 + r)*64 + c4);
        sFt[(c4+0)*132 + r] = v.x;
        sFt[(c4+1)*132 + r] = v.y;
        sFt[(c4+2)*132 + r] = v.z;
        sFt[(c4+3)*132 + r] = v.w;
    }
    int tm = tid >> 5, tn = tid & 31, c0 = tn * 2;
    int mbase = tm << 4;
    const float* Ws[3] = {wq, wk, wv};
    float* Os[3] = {g_q, g_kf, g_vf};
    for (int mat = 0; mat < 3; mat++) {
        __syncthreads();
        for (int i = tid; i < 1024; i += 256)
            *(float4*)(sW + i*4) = *(const float4*)(Ws[mat] + i*4);
        __syncthreads();
        unsigned long long a0[8], a1[8];
        #pragma unroll
        for (int p = 0; p < 8; p++) { a0[p] = 0ull; a1[p] = 0ull; }
        gemm_f32x2(sFt, sW, mbase, c0, a0, a1);
        float* O = Os[mat];
        #pragma unroll
        for (int p = 0; p < 8; p++) {
            float2 r0 = up2(a0[p]);
            float2 r1 = up2(a1[p]);
            *(float2*)(O + (size_t)(R0 + mbase + 2*p)*64 + c0)   = make_float2(r0.x, r1.x);
            *(float2*)(O + (size_t)(R0 + mbase + 2*p+1)*64 + c0) = make_float2(r0.y, r1.y);
        }
    }
}

// ---------------- K3: mega fused kernel ----------------
#define FUSED_SMEM ((64*132 + 3*64*64 + 192 + 256 + 128)*4)
__global__ void __launch_bounds__(256, 2) fused_kernel(
    const float* __restrict__ xyz, const float* __restrict__ feats,
    const float* __restrict__ w1d, const float* __restrict__ b1d,
    const float* __restrict__ w2d, const float* __restrict__ b2d,
    const float* __restrict__ w1g, const float* __restrict__ b1g,
    const float* __restrict__ w2g, const float* __restrict__ b2g)
{
    extern __shared__ float sm[];
    float* sA   = sm;                 // [64][132]
    float* sW2d = sA   + 64*132;      // [64][64]
    float* sW1g = sW2d + 4096;
    float* sW2g = sW1g + 4096;
    float* sW1d = sW2g + 4096;        // [3][64]
    float* sB   = sW1d + 192;         // b1d|b2d|b1g|b2g
    int*   sIdx = (int*)(sB + 256);   // [128]
    int tid = threadIdx.x;

    for (int i = tid; i < 1024; i += 256) {
        *(float4*)(sW2d + i*4) = *(const float4*)(w2d + i*4);
        *(float4*)(sW1g + i*4) = *(const float4*)(w1g + i*4);
        *(float4*)(sW2g + i*4) = *(const float4*)(w2g + i*4);
    }
    if (tid < 192) sW1d[tid] = w1d[tid];
    if (tid < 64) { sB[tid] = b1d[tid]; sB[64+tid] = b2d[tid]; sB[128+tid] = b1g[tid]; sB[192+tid] = b2g[tid]; }

    int R0 = blockIdx.x * 128;
    int P0 = blockIdx.x * 8;
    int b  = P0 >> 13;
    __syncthreads();

    // ---- stage H1 = relu(dxyz @ W1d + b1d) into sA (k-major) ----
    {
        int m   = tid >> 1;
        int row = R0 + m;
        int pn  = row >> 4;
        int nl  = pn & (NN - 1);
        int j   = g_knn[row];
        if ((tid & 1) == 0) sIdx[m] = j;
        const float* xb = xyz + (size_t)b * NN * 3;
        float dx = xb[nl*3+0] - xb[j*3+0];
        float dy = xb[nl*3+1] - xb[j*3+1];
        float dz = xb[nl*3+2] - xb[j*3+2];
        int cb = (tid & 1) * 32;
        #pragma unroll 8
        for (int c = 0; c < 32; c++) {
            int cc = cb + c;
            float h = fmaf(dz, sW1d[128+cc], fmaf(dy, sW1d[64+cc], fmaf(dx, sW1d[cc], sB[cc])));
            sA[cc*132 + m] = fmaxf(h, 0.f);
        }
    }
    __syncthreads();

    int tm = tid >> 5, tn = tid & 31, c0 = tn * 2;
    int mbase = tm << 4;
    int pn0 = P0 + tm;

    // ---- GEMM1: pos = H1 @ W2d + b2d ----
    unsigned long long a0[8], a1[8];
    {
        unsigned long long bb0 = pk2(sB[64+c0],   sB[64+c0]);
        unsigned long long bb1 = pk2(sB[64+c0+1], sB[64+c0+1]);
        #pragma unroll
        for (int p = 0; p < 8; p++) { a0[p] = bb0; a1[p] = bb1; }
        gemm_f32x2(sA, sW2d, mbase, c0, a0, a1);
    }
    __syncthreads();

    // ---- epilogue: x = q - kf + pos -> sA ; val = vf + pos -> v0/v1 ----
    float v0[KNBR], v1[KNBR];
    {
        float2 qv = *(const float2*)(g_q + (size_t)pn0*64 + c0);
        #pragma unroll
        for (int p = 0; p < 8; p++) {
            float2 ps0 = up2(a0[p]);
            float2 ps1 = up2(a1[p]);
            int j0 = sIdx[mbase + 2*p];
            int j1 = sIdx[mbase + 2*p + 1];
            size_t gp0 = ((size_t)(b*NN + j0))*64 + c0;
            size_t gp1 = ((size_t)(b*NN + j1))*64 + c0;
            float2 kf0 = *(const float2*)(g_kf + gp0);
            float2 kf1 = *(const float2*)(g_kf + gp1);
            float2 vf0 = *(const float2*)(g_vf + gp0);
            float2 vf1 = *(const float2*)(g_vf + gp1);
            v0[2*p]   = vf0.x + ps0.x;  v1[2*p]   = vf0.y + ps1.x;
            v0[2*p+1] = vf1.x + ps0.y;  v1[2*p+1] = vf1.y + ps1.y;
            *(float2*)(sA + c0*132     + mbase + 2*p) = make_float2(qv.x - kf0.x + ps0.x, qv.x - kf1.x + ps0.y);
            *(float2*)(sA + (c0+1)*132 + mbase + 2*p) = make_float2(qv.y - kf0.y + ps1.x, qv.y - kf1.y + ps1.y);
        }
    }
    __syncthreads();

    // ---- GEMM2: g1 = relu(x @ W1g + b1g) ----
    {
        unsigned long long bb0 = pk2(sB[128+c0],   sB[128+c0]);
        unsigned long long bb1 = pk2(sB[128+c0+1], sB[128+c0+1]);
        #pragma unroll
        for (int p = 0; p < 8; p++) { a0[p] = bb0; a1[p] = bb1; }
        gemm_f32x2(sA, sW1g, mbase, c0, a0, a1);
    }
    __syncthreads();
    #pragma unroll
    for (int p = 0; p < 8; p++) {
        float2 r0 = up2(a0[p]), r1 = up2(a1[p]);
        *(float2*)(sA + c0*132     + mbase + 2*p) = make_float2(fmaxf(r0.x,0.f), fmaxf(r0.y,0.f));
        *(float2*)(sA + (c0+1)*132 + mbase + 2*p) = make_float2(fmaxf(r1.x,0.f), fmaxf(r1.y,0.f));
    }
    __syncthreads();

    // ---- GEMM3: logits = g1 @ W2g + b2g ----
    {
        unsigned long long bb0 = pk2(sB[192+c0],   sB[192+c0]);
        unsigned long long bb1 = pk2(sB[192+c0+1], sB[192+c0+1]);
        #pragma unroll
        for (int p = 0; p < 8; p++) { a0[p] = bb0; a1[p] = bb1; }
        gemm_f32x2(sA, sW2g, mbase, c0, a0, a1);
    }

    // ---- softmax over K (thread-local) + weighted sum + residual ----
    float t0a[KNBR], t1a[KNBR];
    #pragma unroll
    for (int p = 0; p < 8; p++) {
        float2 r0 = up2(a0[p]), r1 = up2(a1[p]);
        t0a[2*p] = r0.x; t0a[2*p+1] = r0.y;
        t1a[2*p] = r1.x; t1a[2*p+1] = r1.y;
    }
    float m0 = t0a[0], m1 = t1a[0];
    #pragma unroll
    for (int s = 1; s < KNBR; s++) { m0 = fmaxf(m0, t0a[s]); m1 = fmaxf(m1, t1a[s]); }
    float s0 = 0.f, s1 = 0.f;
    #pragma unroll
    for (int s = 0; s < KNBR; s++) {
        t0a[s] = __expf(t0a[s] - m0);  s0 += t0a[s];
        t1a[s] = __expf(t1a[s] - m1);  s1 += t1a[s];
    }
    float r0 = 0.f, r1 = 0.f;
    #pragma unroll
    for (int s = 0; s < KNBR; s++) { r0 = fmaf(t0a[s], v0[s], r0); r1 = fmaf(t1a[s], v1[s], r1); }
    float2 fv = *(const float2*)(feats + (size_t)pn0*64 + c0);
    r0 = r0 / s0 + fv.x;
    r1 = r1 / s1 + fv.y;
    *(float2*)(g_res + (size_t)pn0*64 + c0) = make_float2(r0, r1);

    // ---- BN partial sums ----
    __syncthreads();
    if (tid < 128) sA[tid] = 0.f;
    __syncthreads();
    atomicAdd(&sA[c0],      r0);
    atomicAdd(&sA[c0+1],    r1);
    atomicAdd(&sA[64+c0],   r0*r0);
    atomicAdd(&sA[64+c0+1], r1*r1);
    __syncthreads();
    if (tid < 64) {
        atomicAdd(&g_sum[tid],   sA[tid]);
        atomicAdd(&g_sumsq[tid], sA[64+tid]);
    }
}

// ---------------- K4: BatchNorm apply ----------------
__global__ void __launch_bounds__(256) bn_kernel(
    const float* __restrict__ bn_gamma, const float* __restrict__ bn_beta,
    float* __restrict__ out)
{
    int idx = blockIdx.x * 256 + threadIdx.x;
    int c = idx & 63;
    float inv = 1.0f / (float)NPTS;
    float mean = g_sum[c] * inv;
    float var  = g_sumsq[c] * inv - mean * mean;
    out[idx] = (g_res[idx] - mean) * rsqrtf(var + 1e-5f) * bn_gamma[c] + bn_beta[c];
}

// ---------------- launch ----------------
extern "C" void kernel_launch(void* const* d_in, const int* in_sizes, int n_in,
                              void* d_out, int out_size)
{
    const float* xyz   = (const float*)d_in[0];
    const float* feats = (const float*)d_in[1];
    const float* wq    = (const float*)d_in[2];
    const float* wk    = (const float*)d_in[3];
    const float* wv    = (const float*)d_in[4];
    const float* dw1   = (const float*)d_in[5];
    const float* db1   = (const float*)d_in[6];
    const float* dw2   = (const float*)d_in[7];
    const float* db2   = (const float*)d_in[8];
    const float* gw1   = (const float*)d_in[9];
    const float* gb1   = (const float*)d_in[10];
    const float* gw2   = (const float*)d_in[11];
    const float* gb2   = (const float*)d_in[12];
    const float* bng   = (const float*)d_in[13];
    const float* bnb   = (const float*)d_in[14];
    float* out = (float*)d_out;

    cudaFuncSetAttribute(proj_kernel,  cudaFuncAttributeMaxDynamicSharedMemorySize, PROJ_SMEM);
    cudaFuncSetAttribute(fused_kernel, cudaFuncAttributeMaxDynamicSharedMemorySize, FUSED_SMEM);

    zero_kernel      <<<(BB*GD3)/1024, 1024>>>();
    count_kernel     <<<NPTS/256, 256>>>(xyz);
    scan_kernel      <<<BB, 1024>>>();
    scatter_kernel   <<<NPTS/256, 256>>>(xyz);
    knn_search_kernel<<<NPTS/8, 256>>>();     // 8 warps/block, 1 warp per query
    proj_kernel      <<<128, 256, PROJ_SMEM>>>(feats, wq, wk, wv);
    fused_kernel     <<<2048, 256, FUSED_SMEM>>>(xyz, feats, dw1, db1, dw2, db2, gw1, gb1, gw2, gb2);
    bn_kernel        <<<4096, 256>>>(bng, bnb, out);
}

// round 8
// speedup vs baseline: 2.5222x; 1.2405x over previous
#include <cuda_runtime.h>
#include <math.h>

#define BB 2
#define NN 8192
#define DD 64
#define KNBR 16
#define NPTS (BB*NN)          // 16384
#define ROWS (NPTS*KNBR)      // 262144

// ---- spatial grid for KNN ----
#define GD   64
#define GD3  (GD*GD*GD)       // 262144
#define CPT  256              // cells per scan thread (1024*256 == GD3)
#define XMIN (-8.0f)
#define HCELL 0.25f
#define INVH  4.0f

// ---------------- scratch (static device arrays; no allocation) ----------------
__device__ float  g_q  [NPTS*DD];
__device__ float  g_kf [NPTS*DD];
__device__ float  g_vf [NPTS*DD];
__device__ int    g_knn[ROWS];
__device__ float  g_res[NPTS*DD];
__device__ float  g_sum[DD];
__device__ float  g_sumsq[DD];
__device__ int    g_cnt  [BB*GD3];
__device__ int    g_start[BB*(GD3+1)];
__device__ int    g_cur  [BB*GD3];
__device__ float4 g_pts  [NPTS];     // cell-sorted (x,y,z,|p|^2) per batch
__device__ int    g_sid  [NPTS];     // original index of sorted point

// ---------------- packed f32x2 helpers ----------------
__device__ __forceinline__ void fma2(unsigned long long &d, unsigned long long a, unsigned long long b) {
    asm("fma.rn.f32x2 %0, %1, %2, %0;" : "+l"(d) : "l"(a), "l"(b));
}
__device__ __forceinline__ unsigned long long pk2(float lo, float hi) {
    unsigned long long r; asm("mov.b64 %0, {%1,%2};" : "=l"(r) : "f"(lo), "f"(hi)); return r;
}
__device__ __forceinline__ float2 up2(unsigned long long v) {
    float2 r; asm("mov.b64 {%0,%1}, %2;" : "=f"(r.x), "=f"(r.y) : "l"(v)); return r;
}

// 128x64 GEMM slice. sA: k-major [64][132]; sW: row-major [64][64].
__device__ __forceinline__ void gemm_f32x2(const float* __restrict__ sA, const float* __restrict__ sW,
                                           int mbase, int c0,
                                           unsigned long long* a0, unsigned long long* a1)
{
    #pragma unroll 4
    for (int kk = 0; kk < 64; kk++) {
        const ulonglong2* ap = (const ulonglong2*)(sA + kk*132 + mbase);   // broadcast LDS.128
        float2 w = *(const float2*)(sW + kk*64 + c0);                      // LDS.64
        unsigned long long w0 = pk2(w.x, w.x);
        unsigned long long w1 = pk2(w.y, w.y);
        ulonglong2 A0 = ap[0], A1 = ap[1];
        fma2(a0[0], A0.x, w0); fma2(a1[0], A0.x, w1);
        fma2(a0[1], A0.y, w0); fma2(a1[1], A0.y, w1);
        fma2(a0[2], A1.x, w0); fma2(a1[2], A1.x, w1);
        fma2(a0[3], A1.y, w0); fma2(a1[3], A1.y, w1);
        ulonglong2 A2 = ap[2], A3 = ap[3];
        fma2(a0[4], A2.x, w0); fma2(a1[4], A2.x, w1);
        fma2(a0[5], A2.y, w0); fma2(a1[5], A2.y, w1);
        fma2(a0[6], A3.x, w0); fma2(a1[6], A3.x, w1);
        fma2(a0[7], A3.y, w0); fma2(a1[7], A3.y, w1);
    }
}

// ---------------- grid build ----------------
__device__ __forceinline__ int cellCoord(float v) {
    int c = (int)((v - XMIN) * INVH);
    return min(max(c, 0), GD-1);
}

__global__ void __launch_bounds__(1024) zero_kernel() {
    int i = blockIdx.x * 1024 + threadIdx.x;       // 512*1024 == BB*GD3
    g_cnt[i] = 0;
    if (i < 64) { g_sum[i] = 0.f; g_sumsq[i] = 0.f; }
}

__global__ void __launch_bounds__(256) count_kernel(const float* __restrict__ xyz) {
    int t = blockIdx.x * 256 + threadIdx.x;        // 64*256 == NPTS
    int b = t >> 13, i = t & (NN-1);
    const float* p = xyz + ((size_t)b*NN + i)*3;
    float x = p[0], y = p[1], z = p[2];
    int c = (cellCoord(z)*GD + cellCoord(y))*GD + cellCoord(x);
    atomicAdd(&g_cnt[b*GD3 + c], 1);
}

__global__ void __launch_bounds__(1024) scan_kernel() {
    __shared__ int ssum[1024];
    int b = blockIdx.x, tid = threadIdx.x;
    const int* cnt = g_cnt + b*GD3;
    int* start = g_start + b*(GD3+1);
    int base = tid * CPT;
    int s = 0;
    for (int k = 0; k < CPT; k++) s += cnt[base + k];
    ssum[tid] = s;
    __syncthreads();
    for (int d = 1; d < 1024; d <<= 1) {
        int v = (tid >= d) ? ssum[tid - d] : 0;
        __syncthreads();
        ssum[tid] += v;
        __syncthreads();
    }
    int run = (tid == 0) ? 0 : ssum[tid - 1];
    for (int k = 0; k < CPT; k++) {
        start[base + k] = run;
        g_cur[b*GD3 + base + k] = run;
        run += cnt[base + k];
    }
    if (tid == 1023) start[GD3] = run;
}

__global__ void __launch_bounds__(256) scatter_kernel(const float* __restrict__ xyz) {
    int t = blockIdx.x * 256 + threadIdx.x;
    int b = t >> 13, i = t & (NN-1);
    const float* p = xyz + ((size_t)b*NN + i)*3;
    float x = p[0], y = p[1], z = p[2];
    int c = (cellCoord(z)*GD + cellCoord(y))*GD + cellCoord(x);
    int pos = atomicAdd(&g_cur[b*GD3 + c], 1);
    g_pts[b*NN + pos] = make_float4(x, y, z, fmaf(z, z, fmaf(y, y, x*x)));
    g_sid[b*NN + pos] = i;
}

// ---------------- KNN: warp = 32 sorted queries, shuffle all-pairs ----------------
__device__ __forceinline__ void insert16(float d, int idx, float* d16, int* i16, float& worst) {
    bool done = false;
    #pragma unroll
    for (int s = 0; s < KNBR; s++)
        if (!done && d16[s] == worst) { d16[s] = d; i16[s] = idx; done = true; }
    worst = d16[0];
    #pragma unroll
    for (int s = 1; s < KNBR; s++) worst = fmaxf(worst, d16[s]);
}

// coalesced stream of box candidates; every lane evaluates ALL of them vs its own query
__device__ __forceinline__ void scan_box(
    const int* __restrict__ start, const float4* __restrict__ pts,
    int bxl, int bxh, int byl, int byh, int bzl, int bzh, int S,
    float4 q, int lane, float* d16, int* i16, float& worst)
{
    int zlo = max(bzl-S,0), zhi = min(bzh+S,GD-1);
    int ylo = max(byl-S,0), yhi = min(byh+S,GD-1);
    int xlo = max(bxl-S,0), xhi = min(bxh+S,GD-1);
    for (int zz = zlo; zz <= zhi; zz++) {
        for (int yy = ylo; yy <= yhi; yy++) {
            int cb = (zz*GD + yy)*GD;
            int j0 = start[cb + xlo];          // uniform (broadcast)
            int j1 = start[cb + xhi + 1];
            for (int jb = j0; jb < j1; jb += 32) {
                int jj = jb + lane;
                float4 p = (jj < j1) ? pts[jj] : make_float4(0.f, 0.f, 0.f, 3.4e38f);
                #pragma unroll 8
                for (int r = 0; r < 32; r++) {
                    float px = __shfl_sync(0xffffffffu, p.x, r);
                    float py = __shfl_sync(0xffffffffu, p.y, r);
                    float pz = __shfl_sync(0xffffffffu, p.z, r);
                    float pw = __shfl_sync(0xffffffffu, p.w, r);
                    float dot = fmaf(q.z, pz, fmaf(q.y, py, q.x*px));
                    float d = q.w + pw - 2.0f * dot;   // same expansion form as reference
                    if (d < worst) insert16(d, jb + r, d16, i16, worst);
                }
            }
        }
    }
}

__global__ void __launch_bounds__(64) knn_search_kernel() {
    int t = blockIdx.x * 64 + threadIdx.x;   // query = sorted point index (coalesced)
    int lane = threadIdx.x & 31;
    int b = t >> 13;                         // 32 | 8192: no warp straddles batches
    float4 q = g_pts[t];
    int cx = cellCoord(q.x), cy = cellCoord(q.y), cz = cellCoord(q.z);
    const int* start = g_start + b*(GD3+1);
    const float4* pts = g_pts + (size_t)b*NN;

    // warp bbox of query cells
    int bxl = cx, bxh = cx, byl = cy, byh = cy, bzl = cz, bzh = cz;
    #pragma unroll
    for (int o = 16; o; o >>= 1) {
        bxl = min(bxl, __shfl_xor_sync(0xffffffffu, bxl, o));
        bxh = max(bxh, __shfl_xor_sync(0xffffffffu, bxh, o));
        byl = min(byl, __shfl_xor_sync(0xffffffffu, byl, o));
        byh = max(byh, __shfl_xor_sync(0xffffffffu, byh, o));
        bzl = min(bzl, __shfl_xor_sync(0xffffffffu, bzl, o));
        bzh = max(bzh, __shfl_xor_sync(0xffffffffu, bzh, o));
    }

    float d16[KNBR]; int i16[KNBR];
    #pragma unroll
    for (int i = 0; i < KNBR; i++) { d16[i] = 3.4e38f; i16[i] = 0; }
    float worst = 3.4e38f;

    // ---- pass 1: box(bbox, 1) -> provisional top-16 -> tight radius ----
    scan_box(start, pts, bxl, bxh, byl, byh, bzl, bzh, 1, q, lane, d16, i16, worst);

    // per-lane required Chebyshev radius S (unscanned offset>S => dist >= S*h >= sqrt(worst))
    int S;
    if (worst < 3.3e38f) {
        S = (int)ceilf(sqrtf(worst) * INVH + 0.01f);
    } else {
        // rare: fewer than 16 pts seen; grow count cube (lane-private)
        int s = 2, cnt = 0;
        for (; s < GD; s++) {
            int zl = max(cz-s,0), zh = min(cz+s,GD-1);
            int yl = max(cy-s,0), yh = min(cy+s,GD-1);
            int xl = max(cx-s,0), xh = min(cx+s,GD-1);
            cnt = 0;
            for (int zz = zl; zz <= zh; zz++)
                for (int yy = yl; yy <= yh; yy++) {
                    int cb = (zz*GD + yy)*GD;
                    cnt += start[cb + xh + 1] - start[cb + xl];
                }
            if (cnt >= KNBR) break;
        }
        S = (int)ceilf((float)(s+1) * 1.7320509f) + 1;   // >=16 pts within (s+1)h*sqrt(3)
    }
    #pragma unroll
    for (int o = 16; o; o >>= 1) S = max(S, __shfl_xor_sync(0xffffffffu, S, o));
    if (S > GD) S = GD;

    // ---- pass 2: fresh rescan of box(bbox, S) when pass-1 box insufficient ----
    if (S > 1) {
        #pragma unroll
        for (int i = 0; i < KNBR; i++) { d16[i] = 3.4e38f; i16[i] = 0; }
        worst = 3.4e38f;
        scan_box(start, pts, bxl, bxh, byl, byh, bzl, bzh, S, q, lane, d16, i16, worst);
    }

    // ---- exact per-lane selection already held; sort 16 and write ----
    // (each lane owns ALL candidates for its query, so d16/i16 is the exact top-16)
    int outIdx[KNBR];
    #pragma unroll
    for (int m = 0; m < KNBR; m++) {
        float lm = d16[0]; int lp = 0;
        #pragma unroll
        for (int i = 1; i < KNBR; i++) if (d16[i] < lm) { lm = d16[i]; lp = i; }
        outIdx[m] = i16[lp];
        d16[lp] = 3.4e38f;
    }
    int qi = g_sid[t];
    size_t ob = ((size_t)(b*NN + qi)) * KNBR;
    #pragma unroll
    for (int m = 0; m < KNBR; m++) g_knn[ob + m] = g_sid[(size_t)b*NN + outIdx[m]];
}

// ---------------- K1: projections q,k,v = feats @ W ----------------
#define PROJ_SMEM ((64*132 + 64*64)*4)
__global__ void __launch_bounds__(256) proj_kernel(
    const float* __restrict__ feats,
    const float* __restrict__ wq, const float* __restrict__ wk, const float* __restrict__ wv)
{
    extern __shared__ float sm[];
    float* sFt = sm;            // [64][132] feats^T (k-major)
    float* sW  = sm + 64*132;   // [64][64]
    int tid = threadIdx.x;
    int R0 = blockIdx.x * 128;
    for (int i = tid; i < 128*16; i += 256) {
        int r = i >> 4, c4 = (i & 15) << 2;
        float4 v = *(const float4*)(feats + (size_t)(R0 + r)*64 + c4);
        sFt[(c4+0)*132 + r] = v.x;
        sFt[(c4+1)*132 + r] = v.y;
        sFt[(c4+2)*132 + r] = v.z;
        sFt[(c4+3)*132 + r] = v.w;
    }
    int tm = tid >> 5, tn = tid & 31, c0 = tn * 2;
    int mbase = tm << 4;
    const float* Ws[3] = {wq, wk, wv};
    float* Os[3] = {g_q, g_kf, g_vf};
    for (int mat = 0; mat < 3; mat++) {
        __syncthreads();
        for (int i = tid; i < 1024; i += 256)
            *(float4*)(sW + i*4) = *(const float4*)(Ws[mat] + i*4);
        __syncthreads();
        unsigned long long a0[8], a1[8];
        #pragma unroll
        for (int p = 0; p < 8; p++) { a0[p] = 0ull; a1[p] = 0ull; }
        gemm_f32x2(sFt, sW, mbase, c0, a0, a1);
        float* O = Os[mat];
        #pragma unroll
        for (int p = 0; p < 8; p++) {
            float2 r0 = up2(a0[p]);
            float2 r1 = up2(a1[p]);
            *(float2*)(O + (size_t)(R0 + mbase + 2*p)*64 + c0)   = make_float2(r0.x, r1.x);
            *(float2*)(O + (size_t)(R0 + mbase + 2*p+1)*64 + c0) = make_float2(r0.y, r1.y);
        }
    }
}

// ---------------- K3: mega fused kernel ----------------
#define FUSED_SMEM ((64*132 + 3*64*64 + 192 + 256 + 128)*4)
__global__ void __launch_bounds__(256, 2) fused_kernel(
    const float* __restrict__ xyz, const float* __restrict__ feats,
    const float* __restrict__ w1d, const float* __restrict__ b1d,
    const float* __restrict__ w2d, const float* __restrict__ b2d,
    const float* __restrict__ w1g, const float* __restrict__ b1g,
    const float* __restrict__ w2g, const float* __restrict__ b2g)
{
    extern __shared__ float sm[];
    float* sA   = sm;                 // [64][132]
    float* sW2d = sA   + 64*132;      // [64][64]
    float* sW1g = sW2d + 4096;
    float* sW2g = sW1g + 4096;
    float* sW1d = sW2g + 4096;        // [3][64]
    float* sB   = sW1d + 192;         // b1d|b2d|b1g|b2g
    int*   sIdx = (int*)(sB + 256);   // [128]
    int tid = threadIdx.x;

    for (int i = tid; i < 1024; i += 256) {
        *(float4*)(sW2d + i*4) = *(const float4*)(w2d + i*4);
        *(float4*)(sW1g + i*4) = *(const float4*)(w1g + i*4);
        *(float4*)(sW2g + i*4) = *(const float4*)(w2g + i*4);
    }
    if (tid < 192) sW1d[tid] = w1d[tid];
    if (tid < 64) { sB[tid] = b1d[tid]; sB[64+tid] = b2d[tid]; sB[128+tid] = b1g[tid]; sB[192+tid] = b2g[tid]; }

    int R0 = blockIdx.x * 128;
    int P0 = blockIdx.x * 8;
    int b  = P0 >> 13;
    __syncthreads();

    // ---- stage H1 = relu(dxyz @ W1d + b1d) into sA (k-major) ----
    {
        int m   = tid >> 1;
        int row = R0 + m;
        int pn  = row >> 4;
        int nl  = pn & (NN - 1);
        int j   = g_knn[row];
        if ((tid & 1) == 0) sIdx[m] = j;
        const float* xb = xyz + (size_t)b * NN * 3;
        float dx = xb[nl*3+0] - xb[j*3+0];
        float dy = xb[nl*3+1] - xb[j*3+1];
        float dz = xb[nl*3+2] - xb[j*3+2];
        int cb = (tid & 1) * 32;
        #pragma unroll 8
        for (int c = 0; c < 32; c++) {
            int cc = cb + c;
            float h = fmaf(dz, sW1d[128+cc], fmaf(dy, sW1d[64+cc], fmaf(dx, sW1d[cc], sB[cc])));
            sA[cc*132 + m] = fmaxf(h, 0.f);
        }
    }
    __syncthreads();

    int tm = tid >> 5, tn = tid & 31, c0 = tn * 2;
    int mbase = tm << 4;
    int pn0 = P0 + tm;

    // ---- GEMM1: pos = H1 @ W2d + b2d ----
    unsigned long long a0[8], a1[8];
    {
        unsigned long long bb0 = pk2(sB[64+c0],   sB[64+c0]);
        unsigned long long bb1 = pk2(sB[64+c0+1], sB[64+c0+1]);
        #pragma unroll
        for (int p = 0; p < 8; p++) { a0[p] = bb0; a1[p] = bb1; }
        gemm_f32x2(sA, sW2d, mbase, c0, a0, a1);
    }
    __syncthreads();

    // ---- epilogue: x = q - kf + pos -> sA ; val = vf + pos -> v0/v1 ----
    float v0[KNBR], v1[KNBR];
    {
        float2 qv = *(const float2*)(g_q + (size_t)pn0*64 + c0);
        #pragma unroll
        for (int p = 0; p < 8; p++) {
            float2 ps0 = up2(a0[p]);
            float2 ps1 = up2(a1[p]);
            int j0 = sIdx[mbase + 2*p];
            int j1 = sIdx[mbase + 2*p + 1];
            size_t gp0 = ((size_t)(b*NN + j0))*64 + c0;
            size_t gp1 = ((size_t)(b*NN + j1))*64 + c0;
            float2 kf0 = *(const float2*)(g_kf + gp0);
            float2 kf1 = *(const float2*)(g_kf + gp1);
            float2 vf0 = *(const float2*)(g_vf + gp0);
            float2 vf1 = *(const float2*)(g_vf + gp1);
            v0[2*p]   = vf0.x + ps0.x;  v1[2*p]   = vf0.y + ps1.x;
            v0[2*p+1] = vf1.x + ps0.y;  v1[2*p+1] = vf1.y + ps1.y;
            *(float2*)(sA + c0*132     + mbase + 2*p) = make_float2(qv.x - kf0.x + ps0.x, qv.x - kf1.x + ps0.y);
            *(float2*)(sA + (c0+1)*132 + mbase + 2*p) = make_float2(qv.y - kf0.y + ps1.x, qv.y - kf1.y + ps1.y);
        }
    }
    __syncthreads();

    // ---- GEMM2: g1 = relu(x @ W1g + b1g) ----
    {
        unsigned long long bb0 = pk2(sB[128+c0],   sB[128+c0]);
        unsigned long long bb1 = pk2(sB[128+c0+1], sB[128+c0+1]);
        #pragma unroll
        for (int p = 0; p < 8; p++) { a0[p] = bb0; a1[p] = bb1; }
        gemm_f32x2(sA, sW1g, mbase, c0, a0, a1);
    }
    __syncthreads();
    #pragma unroll
    for (int p = 0; p < 8; p++) {
        float2 r0 = up2(a0[p]), r1 = up2(a1[p]);
        *(float2*)(sA + c0*132     + mbase + 2*p) = make_float2(fmaxf(r0.x,0.f), fmaxf(r0.y,0.f));
        *(float2*)(sA + (c0+1)*132 + mbase + 2*p) = make_float2(fmaxf(r1.x,0.f), fmaxf(r1.y,0.f));
    }
    __syncthreads();

    // ---- GEMM3: logits = g1 @ W2g + b2g ----
    {
        unsigned long long bb0 = pk2(sB[192+c0],   sB[192+c0]);
        unsigned long long bb1 = pk2(sB[192+c0+1], sB[192+c0+1]);
        #pragma unroll
        for (int p = 0; p < 8; p++) { a0[p] = bb0; a1[p] = bb1; }
        gemm_f32x2(sA, sW2g, mbase, c0, a0, a1);
    }

    // ---- softmax over K (thread-local) + weighted sum + residual ----
    float t0a[KNBR], t1a[KNBR];
    #pragma unroll
    for (int p = 0; p < 8; p++) {
        float2 r0 = up2(a0[p]), r1 = up2(a1[p]);
        t0a[2*p] = r0.x; t0a[2*p+1] = r0.y;
        t1a[2*p] = r1.x; t1a[2*p+1] = r1.y;
    }
    float m0 = t0a[0], m1 = t1a[0];
    #pragma unroll
    for (int s = 1; s < KNBR; s++) { m0 = fmaxf(m0, t0a[s]); m1 = fmaxf(m1, t1a[s]); }
    float s0 = 0.f, s1 = 0.f;
    #pragma unroll
    for (int s = 0; s < KNBR; s++) {
        t0a[s] = __expf(t0a[s] - m0);  s0 += t0a[s];
        t1a[s] = __expf(t1a[s] - m1);  s1 += t1a[s];
    }
    float r0 = 0.f, r1 = 0.f;
    #pragma unroll
    for (int s = 0; s < KNBR; s++) { r0 = fmaf(t0a[s], v0[s], r0); r1 = fmaf(t1a[s], v1[s], r1); }
    float2 fv = *(const float2*)(feats + (size_t)pn0*64 + c0);
    r0 = r0 / s0 + fv.x;
    r1 = r1 / s1 + fv.y;
    *(float2*)(g_res + (size_t)pn0*64 + c0) = make_float2(r0, r1);

    // ---- BN partial sums ----
    __syncthreads();
    if (tid < 128) sA[tid] = 0.f;
    __syncthreads();
    atomicAdd(&sA[c0],      r0);
    atomicAdd(&sA[c0+1],    r1);
    atomicAdd(&sA[64+c0],   r0*r0);
    atomicAdd(&sA[64+c0+1], r1*r1);
    __syncthreads();
    if (tid < 64) {
        atomicAdd(&g_sum[tid],   sA[tid]);
        atomicAdd(&g_sumsq[tid], sA[64+tid]);
    }
}

// ---------------- K4: BatchNorm apply ----------------
__global__ void __launch_bounds__(256) bn_kernel(
    const float* __restrict__ bn_gamma, const float* __restrict__ bn_beta,
    float* __restrict__ out)
{
    int idx = blockIdx.x * 256 + threadIdx.x;
    int c = idx & 63;
    float inv = 1.0f / (float)NPTS;
    float mean = g_sum[c] * inv;
    float var  = g_sumsq[c] * inv - mean * mean;
    out[idx] = (g_res[idx] - mean) * rsqrtf(var + 1e-5f) * bn_gamma[c] + bn_beta[c];
}

// ---------------- launch ----------------
extern "C" void kernel_launch(void* const* d_in, const int* in_sizes, int n_in,
                              void* d_out, int out_size)
{
    const float* xyz   = (const float*)d_in[0];
    const float* feats = (const float*)d_in[1];
    const float* wq    = (const float*)d_in[2];
    const float* wk    = (const float*)d_in[3];
    const float* wv    = (const float*)d_in[4];
    const float* dw1   = (const float*)d_in[5];
    const float* db1   = (const float*)d_in[6];
    const float* dw2   = (const float*)d_in[7];
    const float* db2   = (const float*)d_in[8];
    const float* gw1   = (const float*)d_in[9];
    const float* gb1   = (const float*)d_in[10];
    const float* gw2   = (const float*)d_in[11];
    const float* gb2   = (const float*)d_in[12];
    const float* bng   = (const float*)d_in[13];
    const float* bnb   = (const float*)d_in[14];
    float* out = (float*)d_out;

    cudaFuncSetAttribute(proj_kernel,  cudaFuncAttributeMaxDynamicSharedMemorySize, PROJ_SMEM);
    cudaFuncSetAttribute(fused_kernel, cudaFuncAttributeMaxDynamicSharedMemorySize, FUSED_SMEM);

    zero_kernel      <<<(BB*GD3)/1024, 1024>>>();
    count_kernel     <<<NPTS/256, 256>>>(xyz);
    scan_kernel      <<<BB, 1024>>>();
    scatter_kernel   <<<NPTS/256, 256>>>(xyz);
    knn_search_kernel<<<NPTS/64, 64>>>();     // warp = 32 cell-sorted queries
    proj_kernel      <<<128, 256, PROJ_SMEM>>>(feats, wq, wk, wv);
    fused_kernel     <<<2048, 256, FUSED_SMEM>>>(xyz, feats, dw1, db1, dw2, db2, gw1, gb1, gw2, gb2);
    bn_kernel        <<<4096, 256>>>(bng, bnb, out);
}